// round 7
// baseline (speedup 1.0000x reference)
#include <cuda_runtime.h>
#include <cuda_bf16.h>
#include <math.h>
#include <cstdint>

#define BB   2
#define SEQ  2048
#define HIDN 2048
#define NH   16
#define NKV  4
#define HD   128

// ============================================================
// helpers
// ============================================================
__device__ __forceinline__ uint32_t smem_u32(const void* p) {
    uint32_t a;
    asm("{ .reg .u64 t; cvta.to.shared.u64 t, %1; cvt.u32.u64 %0, t; }" : "=r"(a) : "l"(p));
    return a;
}
__device__ __forceinline__ void ldsm_x4(uint32_t& r0, uint32_t& r1, uint32_t& r2, uint32_t& r3,
                                        uint32_t addr) {
    asm volatile("ldmatrix.sync.aligned.m8n8.x4.shared.b16 {%0,%1,%2,%3}, [%4];"
                 : "=r"(r0), "=r"(r1), "=r"(r2), "=r"(r3) : "r"(addr));
}
__device__ __forceinline__ void ldsm_x4_t(uint32_t& r0, uint32_t& r1, uint32_t& r2, uint32_t& r3,
                                          uint32_t addr) {
    asm volatile("ldmatrix.sync.aligned.m8n8.x4.trans.shared.b16 {%0,%1,%2,%3}, [%4];"
                 : "=r"(r0), "=r"(r1), "=r"(r2), "=r"(r3) : "r"(addr));
}
__device__ __forceinline__ void mma_bf16(float* c, const uint32_t* a, const uint32_t* b) {
    asm volatile("mma.sync.aligned.m16n8k16.row.col.f32.bf16.bf16.f32 "
                 "{%0,%1,%2,%3}, {%4,%5,%6,%7}, {%8,%9}, {%0,%1,%2,%3};"
                 : "+f"(c[0]), "+f"(c[1]), "+f"(c[2]), "+f"(c[3])
                 : "r"(a[0]), "r"(a[1]), "r"(a[2]), "r"(a[3]), "r"(b[0]), "r"(b[1]));
}
__device__ __forceinline__ void cp_async16(uint32_t saddr, const void* gptr) {
    asm volatile("cp.async.cg.shared.global [%0], [%1], 16;"
                 :: "r"(saddr), "l"(__cvta_generic_to_global(gptr)));
}
// fast 2^t on the FMA pipe, t <= 0
__device__ __forceinline__ float fexp2(float t) {
    t = fmaxf(t, -126.0f);
    float fi = floorf(t);
    float f = t - fi;
    float p =             1.5403530e-4f;
    p = fmaf(p, f, 1.3333558e-3f);
    p = fmaf(p, f, 9.6181291e-3f);
    p = fmaf(p, f, 5.5504109e-2f);
    p = fmaf(p, f, 2.4022651e-1f);
    p = fmaf(p, f, 6.9314718e-1f);
    p = fmaf(p, f, 1.0f);
    return p * __int_as_float(((int)fi + 127) << 23);
}

// -------- scratch (device globals) --------
__device__ float g_q[(size_t)BB * SEQ * NH * HD];
__device__ float g_k[(size_t)BB * SEQ * NKV * HD];
__device__ float g_v[(size_t)BB * SEQ * NKV * HD];

__device__ __nv_bfloat16 g_xh[(size_t)BB * SEQ * HIDN], g_xl[(size_t)BB * SEQ * HIDN];
__device__ __nv_bfloat16 g_wqh[(size_t)HIDN * NH * HD], g_wql[(size_t)HIDN * NH * HD];
__device__ __nv_bfloat16 g_wkh[(size_t)HIDN * NKV * HD], g_wkl[(size_t)HIDN * NKV * HD];
__device__ __nv_bfloat16 g_wvh[(size_t)HIDN * NKV * HD], g_wvl[(size_t)HIDN * NKV * HD];
__device__ __nv_bfloat16 g_woh[(size_t)NH * HD * HIDN], g_wol[(size_t)NH * HD * HIDN];

__device__ __nv_bfloat16 g_qsh[(size_t)BB * NH * SEQ * HD],  g_qsl[(size_t)BB * NH * SEQ * HD];
__device__ __nv_bfloat16 g_ksh[(size_t)BB * NKV * SEQ * HD], g_ksl[(size_t)BB * NKV * SEQ * HD];
__device__ __nv_bfloat16 g_vsh[(size_t)BB * NKV * SEQ * HD], g_vsl[(size_t)BB * NKV * SEQ * HD];
__device__ __nv_bfloat16 g_oh[(size_t)BB * SEQ * NH * HD],  g_ol[(size_t)BB * SEQ * NH * HD];

// ============================================================
// fp32 -> (hi, lo) bf16 split
// ============================================================
__global__ void split_fp32(const float* __restrict__ x,
                           __nv_bfloat16* __restrict__ h, __nv_bfloat16* __restrict__ l, int n)
{
    int i = blockIdx.x * blockDim.x + threadIdx.x;
    if (i < n) {
        float v = x[i];
        __nv_bfloat16 hi = __float2bfloat16(v);
        h[i] = hi;
        l[i] = __float2bfloat16(v - __bfloat162float(hi));
    }
}

// ============================================================
// W[K,N] fp32 -> Wt_hi/Wt_lo [N,K] bf16 (transpose + split)
// ============================================================
__global__ void transpose_split(const float* __restrict__ W,
                                __nv_bfloat16* __restrict__ Th, __nv_bfloat16* __restrict__ Tl,
                                int K, int N)
{
    __shared__ float t[32][33];
    const int n0 = blockIdx.x * 32, k0 = blockIdx.y * 32;
    const int tx = threadIdx.x, ty = threadIdx.y;
    for (int i = ty; i < 32; i += 8)
        t[i][tx] = W[(size_t)(k0 + i) * N + n0 + tx];
    __syncthreads();
    for (int i = ty; i < 32; i += 8) {
        float v = t[tx][i];
        __nv_bfloat16 hi = __float2bfloat16(v);
        float r = v - __bfloat162float(hi);
        Th[(size_t)(n0 + i) * K + k0 + tx] = hi;
        Tl[(size_t)(n0 + i) * K + k0 + tx] = __float2bfloat16(r);
    }
}

#define LDA 40

// ============================================================
// BIG GEMM: CTA 256x128, 8 warps (4x2) each 64x64 warp tile.
// BK=32, 3-stage cp.async pipeline, ONE barrier per chunk.
// C[M,N] = A[M,K] @ B^T (B stored [N,K]); split-bf16 3-term.
// ============================================================
#define BG_AT (256 * LDA * 2)            // one A tile (hi or lo): 20480 B
#define BG_BT (128 * LDA * 2)            // one B tile: 10240 B
#define BG_STAGE (2 * BG_AT + 2 * BG_BT) // 61440 B
#define BG_SMEM (3 * BG_STAGE)           // 184320 B

__global__ void __launch_bounds__(256, 1) gemm_big(
    const __nv_bfloat16* __restrict__ Ah_, const __nv_bfloat16* __restrict__ Al_,
    const __nv_bfloat16* __restrict__ Bh_, const __nv_bfloat16* __restrict__ Bl_,
    float* __restrict__ C, int Nd, int Kd)
{
    extern __shared__ char sm[];
    const uint32_t sb = smem_u32(sm);
    const int tid = threadIdx.x, lane = tid & 31, wid = tid >> 5;
    const int m0 = blockIdx.y * 256, n0 = blockIdx.x * 128;
    const int m_off = (wid >> 1) * 64;
    const int n_off = (wid & 1) * 64;

    const __nv_bfloat16* pAh = Ah_ + (size_t)m0 * Kd;
    const __nv_bfloat16* pAl = Al_ + (size_t)m0 * Kd;
    const __nv_bfloat16* pBh = Bh_ + (size_t)n0 * Kd;
    const __nv_bfloat16* pBl = Bl_ + (size_t)n0 * Kd;

    const int nchunk = Kd >> 5;
    // loader: A tiles 256 rows x 4 16B-units, B tiles 128 x 4
    const int ar = tid >> 2, au = (tid & 3) * 8;   // within A tile (4 iters of 64 rows)
    const int br = tid >> 2, bu = (tid & 3) * 8;   // within B tile (2 iters of 64 rows)

    auto load_chunk = [&](int c) {
        const int k0 = c << 5;
        const uint32_t stg = sb + (uint32_t)(c % 3) * BG_STAGE;
        const uint32_t sAh = stg, sAl = stg + BG_AT;
        const uint32_t sBh = stg + 2 * BG_AT, sBl = stg + 2 * BG_AT + BG_BT;
#pragma unroll
        for (int it = 0; it < 4; it++) {
            const int r = ar + it * 64;
            const uint32_t so = (uint32_t)(r * LDA + au) * 2;
            const size_t go = (size_t)r * Kd + k0 + au;
            cp_async16(sAh + so, pAh + go);
            cp_async16(sAl + so, pAl + go);
        }
#pragma unroll
        for (int it = 0; it < 2; it++) {
            const int r = br + it * 64;
            const uint32_t so = (uint32_t)(r * LDA + bu) * 2;
            const size_t go = (size_t)r * Kd + k0 + bu;
            cp_async16(sBh + so, pBh + go);
            cp_async16(sBl + so, pBl + go);
        }
        asm volatile("cp.async.commit_group;" ::: "memory");
    };

    const int a_row = ((lane >> 3) & 1) * 8 + (lane & 7);
    const int a_kh  = (lane >> 4) * 8;
    const int b_row = ((lane >> 4) & 1) * 8 + (lane & 7);
    const int b_kh  = ((lane >> 3) & 1) * 8;

    float acc[4][8][4];
#pragma unroll
    for (int i = 0; i < 4; i++)
#pragma unroll
        for (int j = 0; j < 8; j++)
#pragma unroll
            for (int q = 0; q < 4; q++) acc[i][j][q] = 0.f;

    load_chunk(0);
    load_chunk(1);

    for (int c = 0; c < nchunk; c++) {
        if (c < nchunk - 1) {
            asm volatile("cp.async.wait_group 1;" ::: "memory");
        } else {
            asm volatile("cp.async.wait_group 0;" ::: "memory");
        }
        __syncthreads();
        // issue c+2 into the stage freed by the barrier (stage (c-1)%3)
        if (c + 2 < nchunk) load_chunk(c + 2);

        const uint32_t stg = sb + (uint32_t)(c % 3) * BG_STAGE;
        const uint32_t sAh = stg, sAl = stg + BG_AT;
        const uint32_t sBh = stg + 2 * BG_AT, sBl = stg + 2 * BG_AT + BG_BT;

#pragma unroll
        for (int ks = 0; ks < 2; ks++) {
            uint32_t ah[4][4], al[4][4], bh[8][2], bl[8][2];
#pragma unroll
            for (int mi = 0; mi < 4; mi++) {
                const uint32_t off =
                    (uint32_t)((m_off + mi * 16 + a_row) * LDA + ks * 16 + a_kh) * 2;
                ldsm_x4(ah[mi][0], ah[mi][1], ah[mi][2], ah[mi][3], sAh + off);
                ldsm_x4(al[mi][0], al[mi][1], al[mi][2], al[mi][3], sAl + off);
            }
#pragma unroll
            for (int nb = 0; nb < 4; nb++) {
                const uint32_t off =
                    (uint32_t)((n_off + nb * 16 + b_row) * LDA + ks * 16 + b_kh) * 2;
                ldsm_x4(bh[2 * nb][0], bh[2 * nb][1], bh[2 * nb + 1][0], bh[2 * nb + 1][1],
                        sBh + off);
                ldsm_x4(bl[2 * nb][0], bl[2 * nb][1], bl[2 * nb + 1][0], bl[2 * nb + 1][1],
                        sBl + off);
            }
#pragma unroll
            for (int mi = 0; mi < 4; mi++)
#pragma unroll
                for (int ni = 0; ni < 8; ni++) {
                    mma_bf16(acc[mi][ni], ah[mi], bh[ni]);
                    mma_bf16(acc[mi][ni], ah[mi], bl[ni]);
                    mma_bf16(acc[mi][ni], al[mi], bh[ni]);
                }
        }
    }

    const int erow = lane >> 2, ecol = (lane & 3) * 2;
#pragma unroll
    for (int mi = 0; mi < 4; mi++)
#pragma unroll
        for (int ni = 0; ni < 8; ni++) {
            const int row = m0 + m_off + mi * 16 + erow;
            const int col = n0 + n_off + ni * 8 + ecol;
            float2 v0 = make_float2(acc[mi][ni][0], acc[mi][ni][1]);
            float2 v1 = make_float2(acc[mi][ni][2], acc[mi][ni][3]);
            *(float2*)(C + (size_t)row * Nd + col)       = v0;
            *(float2*)(C + (size_t)(row + 8) * Nd + col) = v1;
        }
}

// ============================================================
// 128x128 HMMA GEMM (R4) — used for the narrow K/V projections
// ============================================================
#define GTILE_B (128 * LDA * 2)
#define GSTAGE_B (4 * GTILE_B)
#define GEMM_SMEM (2 * GSTAGE_B)

__global__ void __launch_bounds__(256, 1) gemm_hmma_split(
    const __nv_bfloat16* __restrict__ Ah_, const __nv_bfloat16* __restrict__ Al_,
    const __nv_bfloat16* __restrict__ Bh_, const __nv_bfloat16* __restrict__ Bl_,
    float* __restrict__ C, int Nd, int Kd)
{
    extern __shared__ char sm[];
    const uint32_t sb = smem_u32(sm);
    const int tid = threadIdx.x, lane = tid & 31, wid = tid >> 5;
    const int m0 = blockIdx.y * 128, n0 = blockIdx.x * 128;
    const int m_off = (wid >> 2) * 64;
    const int n_off = (wid & 3) * 32;

    const int r0 = tid >> 2;
    const int c8 = (tid & 3) * 8;

    const __nv_bfloat16* gp[4] = {
        Ah_ + (size_t)m0 * Kd, Al_ + (size_t)m0 * Kd,
        Bh_ + (size_t)n0 * Kd, Bl_ + (size_t)n0 * Kd };

    const int nchunk = Kd >> 5;

    auto load_chunk = [&](int c) {
        const int k0 = c << 5;
        const uint32_t stg = sb + (uint32_t)(c & 1) * GSTAGE_B;
#pragma unroll
        for (int t = 0; t < 4; t++) {
#pragma unroll
            for (int p = 0; p < 2; p++) {
                const int r = r0 + p * 64;
                cp_async16(stg + (uint32_t)t * GTILE_B + (uint32_t)(r * LDA + c8) * 2,
                           gp[t] + (size_t)r * Kd + k0 + c8);
            }
        }
        asm volatile("cp.async.commit_group;" ::: "memory");
    };

    const int a_row = ((lane >> 3) & 1) * 8 + (lane & 7);
    const int a_kh  = (lane >> 4) * 8;
    const int b_row = ((lane >> 4) & 1) * 8 + (lane & 7);
    const int b_kh  = ((lane >> 3) & 1) * 8;

    float acc[4][4][4];
#pragma unroll
    for (int i = 0; i < 4; i++)
#pragma unroll
        for (int j = 0; j < 4; j++)
#pragma unroll
            for (int q = 0; q < 4; q++) acc[i][j][q] = 0.f;

    load_chunk(0);
    for (int c = 0; c < nchunk; c++) {
        if (c + 1 < nchunk) {
            load_chunk(c + 1);
            asm volatile("cp.async.wait_group 1;" ::: "memory");
        } else {
            asm volatile("cp.async.wait_group 0;" ::: "memory");
        }
        __syncthreads();

        const uint32_t stg = sb + (uint32_t)(c & 1) * GSTAGE_B;
        const uint32_t sAh = stg;
        const uint32_t sAl = stg + GTILE_B;
        const uint32_t sBh = stg + 2 * GTILE_B;
        const uint32_t sBl = stg + 3 * GTILE_B;

#pragma unroll
        for (int ks = 0; ks < 2; ks++) {
            uint32_t ah[4][4], al[4][4], bh[4][2], bl[4][2];
#pragma unroll
            for (int mi = 0; mi < 4; mi++) {
                const uint32_t off =
                    (uint32_t)((m_off + mi * 16 + a_row) * LDA + ks * 16 + a_kh) * 2;
                ldsm_x4(ah[mi][0], ah[mi][1], ah[mi][2], ah[mi][3], sAh + off);
                ldsm_x4(al[mi][0], al[mi][1], al[mi][2], al[mi][3], sAl + off);
            }
#pragma unroll
            for (int nb = 0; nb < 2; nb++) {
                const uint32_t off =
                    (uint32_t)((n_off + nb * 16 + b_row) * LDA + ks * 16 + b_kh) * 2;
                ldsm_x4(bh[2 * nb][0], bh[2 * nb][1], bh[2 * nb + 1][0], bh[2 * nb + 1][1],
                        sBh + off);
                ldsm_x4(bl[2 * nb][0], bl[2 * nb][1], bl[2 * nb + 1][0], bl[2 * nb + 1][1],
                        sBl + off);
            }
#pragma unroll
            for (int mi = 0; mi < 4; mi++)
#pragma unroll
                for (int ni = 0; ni < 4; ni++) {
                    mma_bf16(acc[mi][ni], ah[mi], bh[ni]);
                    mma_bf16(acc[mi][ni], ah[mi], bl[ni]);
                    mma_bf16(acc[mi][ni], al[mi], bh[ni]);
                }
        }
        __syncthreads();
    }

    const int erow = lane >> 2, ecol = (lane & 3) * 2;
#pragma unroll
    for (int mi = 0; mi < 4; mi++)
#pragma unroll
        for (int ni = 0; ni < 4; ni++) {
            const int row = m0 + m_off + mi * 16 + erow;
            const int col = n0 + n_off + ni * 8 + ecol;
            float2 v0 = make_float2(acc[mi][ni][0], acc[mi][ni][1]);
            float2 v1 = make_float2(acc[mi][ni][2], acc[mi][ni][3]);
            *(float2*)(C + (size_t)row * Nd + col)       = v0;
            *(float2*)(C + (size_t)(row + 8) * Nd + col) = v1;
        }
}

// ============================================================
// RoPE + split + relayout: src fp32 [b,s,heads,128] -> dst bf16 [b,head,s,128]
// ============================================================
__global__ void rope_split(const float* __restrict__ src,
                           __nv_bfloat16* __restrict__ dh, __nv_bfloat16* __restrict__ dl,
                           int heads)
{
    const int idx = blockIdx.x;
    const int hh = idx % heads;
    const int bs = idx / heads;
    const int s = bs % SEQ, b = bs / SEQ;
    const float* row = src + (size_t)idx * HD;
    const int i = threadIdx.x;

    float x0 = row[2 * i];
    float x1 = row[2 * i + 1];
    float inv = exp2f(-(float)i * (13.287712379549449f / 64.f));
    float ang = (float)s * inv;
    float sn, cs;
    sincosf(ang, &sn, &cs);
    float o0 = x0 * cs - x1 * sn;
    float o1 = x0 * sn + x1 * cs;

    const size_t dst = ((size_t)(b * heads + hh) * SEQ + s) * HD;
    __nv_bfloat16 h0 = __float2bfloat16(o0);
    __nv_bfloat16 h1 = __float2bfloat16(o1);
    dh[dst + i]      = h0;
    dh[dst + i + 64] = h1;
    dl[dst + i]      = __float2bfloat16(o0 - __bfloat162float(h0));
    dl[dst + i + 64] = __float2bfloat16(o1 - __bfloat162float(h1));
}

// ============================================================
// V split + relayout
// ============================================================
__global__ void split_v_kernel(const float* __restrict__ v,
                               __nv_bfloat16* __restrict__ vh, __nv_bfloat16* __restrict__ vl)
{
    const int idx = blockIdx.x;
    const int kv = idx % NKV;
    const int bs = idx / NKV;
    const int s = bs % SEQ, b = bs / SEQ;
    const int i = threadIdx.x;
    float val = v[(size_t)idx * HD + i];
    const size_t dst = ((size_t)(b * NKV + kv) * SEQ + s) * HD + i;
    __nv_bfloat16 h = __float2bfloat16(val);
    vh[dst] = h;
    vl[dst] = __float2bfloat16(val - __bfloat162float(h));
}

// ============================================================
// HMMA flash attention (unchanged from R6)
// ============================================================
#define ALDQ 136
#define ALDS 73
#define ALDP 72
#define A_QH 0
#define A_QL (A_QH + 128 * ALDQ * 2)
#define A_KH (A_QL + 128 * ALDQ * 2)
#define A_KL (A_KH + 64 * ALDQ * 2)
#define A_VH (A_KL + 64 * ALDQ * 2)
#define A_VL (A_VH + 64 * ALDQ * 2)
#define A_SP (A_VL + 64 * ALDQ * 2)
#define A_PH (A_SP + 128 * ALDS * 4)
#define A_PL (A_PH + 128 * ALDP * 2)
#define A_MS (A_PL + 128 * ALDP * 2)
#define A_LS (A_MS + 512)
#define A_FS (A_LS + 512)
#define A_RED (A_FS + 512)
#define ATTN_SMEM_B (A_RED + 1024)

#define SCL2E 0.12751744f

__global__ void __launch_bounds__(256, 1) attn_hmma(
    const __nv_bfloat16* __restrict__ Qh_, const __nv_bfloat16* __restrict__ Ql_,
    const __nv_bfloat16* __restrict__ Kh_, const __nv_bfloat16* __restrict__ Kl_,
    const __nv_bfloat16* __restrict__ Vh_, const __nv_bfloat16* __restrict__ Vl_,
    __nv_bfloat16* __restrict__ Oh_, __nv_bfloat16* __restrict__ Ol_)
{
    extern __shared__ char sm[];
    const uint32_t sb = smem_u32(sm);
    float* Sp  = (float*)(sm + A_SP);
    float* m_s = (float*)(sm + A_MS);
    float* l_s = (float*)(sm + A_LS);
    float* f_s = (float*)(sm + A_FS);
    float* red = (float*)(sm + A_RED);
    __nv_bfloat16* PhP = (__nv_bfloat16*)(sm + A_PH);
    __nv_bfloat16* PlP = (__nv_bfloat16*)(sm + A_PL);

    const int qb = blockIdx.x, h = blockIdx.y, b = blockIdx.z;
    const int kvh = h >> 2;
    const int tid = threadIdx.x, lane = tid & 31, wid = tid >> 5;
    const int q0 = qb * 128;

    const size_t qg = ((size_t)(b * NH + h) * SEQ + q0) * HD;
    const size_t kg = (size_t)(b * NKV + kvh) * SEQ * HD;

    for (int i = tid; i < 128 * 16; i += 256) {
        int r = i >> 4, c = (i & 15) * 8;
        uint32_t so = (uint32_t)(r * ALDQ + c) * 2;
        cp_async16(sb + A_QH + so, Qh_ + qg + (size_t)r * HD + c);
        cp_async16(sb + A_QL + so, Ql_ + qg + (size_t)r * HD + c);
    }
    asm volatile("cp.async.commit_group;" ::: "memory");
    if (tid < 128) { m_s[tid] = -1e30f; l_s[tid] = 0.f; }

    float accO[2][8][4];
#pragma unroll
    for (int i = 0; i < 2; i++)
#pragma unroll
        for (int j = 0; j < 8; j++)
#pragma unroll
            for (int q = 0; q < 4; q++) accO[i][j][q] = 0.f;

    const int m_off = (wid >> 1) * 32;
    const int nS = (wid & 1) * 32;
    const int nO = (wid & 1) * 64;
    const int a_row = ((lane >> 3) & 1) * 8 + (lane & 7);
    const int a_kh  = (lane >> 4) * 8;
    const int b_row = ((lane >> 4) & 1) * 8 + (lane & 7);
    const int b_kh  = ((lane >> 3) & 1) * 8;
    const int erow = lane >> 2, ecol = (lane & 3) * 2;

    asm volatile("cp.async.wait_group 0;" ::: "memory");
    __syncthreads();

    const int ntiles = 2 * qb + 2;
    for (int jb = 0; jb < ntiles; jb++) {
        const int k0 = jb * 64;
        for (int i = tid; i < 64 * 16; i += 256) {
            int r = i >> 4, c = (i & 15) * 8;
            uint32_t so = (uint32_t)(r * ALDQ + c) * 2;
            const size_t g = kg + (size_t)(k0 + r) * HD + c;
            cp_async16(sb + A_KH + so, Kh_ + g);
            cp_async16(sb + A_KL + so, Kl_ + g);
            cp_async16(sb + A_VH + so, Vh_ + g);
            cp_async16(sb + A_VL + so, Vl_ + g);
        }
        asm volatile("cp.async.commit_group;" ::: "memory");
        asm volatile("cp.async.wait_group 0;" ::: "memory");
        __syncthreads();

        float accS[2][4][4];
#pragma unroll
        for (int i = 0; i < 2; i++)
#pragma unroll
            for (int j = 0; j < 4; j++)
#pragma unroll
                for (int q = 0; q < 4; q++) accS[i][j][q] = 0.f;

#pragma unroll
        for (int ks = 0; ks < 8; ks++) {
            uint32_t ah[2][4], al[2][4], bh[4][2], bl[4][2];
#pragma unroll
            for (int mi = 0; mi < 2; mi++) {
                const uint32_t off =
                    (uint32_t)((m_off + mi * 16 + a_row) * ALDQ + ks * 16 + a_kh) * 2;
                ldsm_x4(ah[mi][0], ah[mi][1], ah[mi][2], ah[mi][3], sb + A_QH + off);
                ldsm_x4(al[mi][0], al[mi][1], al[mi][2], al[mi][3], sb + A_QL + off);
            }
#pragma unroll
            for (int nb = 0; nb < 2; nb++) {
                const uint32_t off =
                    (uint32_t)((nS + nb * 16 + b_row) * ALDQ + ks * 16 + b_kh) * 2;
                ldsm_x4(bh[2 * nb][0], bh[2 * nb][1], bh[2 * nb + 1][0], bh[2 * nb + 1][1],
                        sb + A_KH + off);
                ldsm_x4(bl[2 * nb][0], bl[2 * nb][1], bl[2 * nb + 1][0], bl[2 * nb + 1][1],
                        sb + A_KL + off);
            }
#pragma unroll
            for (int mi = 0; mi < 2; mi++)
#pragma unroll
                for (int ni = 0; ni < 4; ni++) {
                    mma_bf16(accS[mi][ni], ah[mi], bh[ni]);
                    mma_bf16(accS[mi][ni], ah[mi], bl[ni]);
                    mma_bf16(accS[mi][ni], al[mi], bh[ni]);
                }
        }

#pragma unroll
        for (int mi = 0; mi < 2; mi++)
#pragma unroll
            for (int ni = 0; ni < 4; ni++) {
                const int row = m_off + mi * 16 + erow;
                const int col = nS + ni * 8 + ecol;
                Sp[row * ALDS + col]           = accS[mi][ni][0] * SCL2E;
                Sp[row * ALDS + col + 1]       = accS[mi][ni][1] * SCL2E;
                Sp[(row + 8) * ALDS + col]     = accS[mi][ni][2] * SCL2E;
                Sp[(row + 8) * ALDS + col + 1] = accS[mi][ni][3] * SCL2E;
            }
        __syncthreads();

        {
            const int row = tid & 127, part = tid >> 7;
            const int cb = part * 32;
            float mx = -1e30f;
#pragma unroll
            for (int c = 0; c < 32; c++) {
                const int cc = cb + c;
                float s = Sp[row * ALDS + cc];
                if (k0 + cc > q0 + row) s = -1e30f;
                mx = fmaxf(mx, s);
            }
            red[part * 128 + row] = mx;
            __syncthreads();
            if (part == 0) {
                float mo = m_s[row];
                float mn = fmaxf(mo, fmaxf(red[row], red[128 + row]));
                m_s[row] = mn;
                f_s[row] = fexp2(mo - mn);
            }
            __syncthreads();
            const float mrow = m_s[row];
            float sum = 0.f;
#pragma unroll
            for (int c = 0; c < 16; c++) {
                const int cc = cb + c * 2;
                float s0 = Sp[row * ALDS + cc];
                float s1 = Sp[row * ALDS + cc + 1];
                float p0 = (k0 + cc     > q0 + row) ? 0.f : fexp2(s0 - mrow);
                float p1 = (k0 + cc + 1 > q0 + row) ? 0.f : fexp2(s1 - mrow);
                sum += p0 + p1;
                __nv_bfloat16 h0 = __float2bfloat16(p0);
                __nv_bfloat16 h1 = __float2bfloat16(p1);
                __nv_bfloat162 hp; hp.x = h0; hp.y = h1;
                *(__nv_bfloat162*)(PhP + row * ALDP + cc) = hp;
                __nv_bfloat162 lp;
                lp.x = __float2bfloat16(p0 - __bfloat162float(h0));
                lp.y = __float2bfloat16(p1 - __bfloat162float(h1));
                *(__nv_bfloat162*)(PlP + row * ALDP + cc) = lp;
            }
            red[part * 128 + row] = sum;
            __syncthreads();
            if (part == 0)
                l_s[row] = l_s[row] * f_s[row] + red[row] + red[128 + row];
        }
        __syncthreads();

#pragma unroll
        for (int mi = 0; mi < 2; mi++) {
            const float f0 = f_s[m_off + mi * 16 + erow];
            const float f1 = f_s[m_off + mi * 16 + erow + 8];
#pragma unroll
            for (int ni = 0; ni < 8; ni++) {
                accO[mi][ni][0] *= f0; accO[mi][ni][1] *= f0;
                accO[mi][ni][2] *= f1; accO[mi][ni][3] *= f1;
            }
        }
#pragma unroll
        for (int kk = 0; kk < 4; kk++) {
            uint32_t ph[2][4], pl[2][4], vh[8][2], vl[8][2];
#pragma unroll
            for (int mi = 0; mi < 2; mi++) {
                const uint32_t off =
                    (uint32_t)((m_off + mi * 16 + a_row) * ALDP + kk * 16 + a_kh) * 2;
                ldsm_x4(ph[mi][0], ph[mi][1], ph[mi][2], ph[mi][3], sb + A_PH + off);
                ldsm_x4(pl[mi][0], pl[mi][1], pl[mi][2], pl[mi][3], sb + A_PL + off);
            }
#pragma unroll
            for (int nb = 0; nb < 4; nb++) {
                const int vr = kk * 16 + ((lane >> 3) & 1) * 8 + (lane & 7);
                const int vc = nO + nb * 16 + ((lane >> 4) & 1) * 8;
                const uint32_t off = (uint32_t)(vr * ALDQ + vc) * 2;
                ldsm_x4_t(vh[2 * nb][0], vh[2 * nb][1], vh[2 * nb + 1][0], vh[2 * nb + 1][1],
                          sb + A_VH + off);
                ldsm_x4_t(vl[2 * nb][0], vl[2 * nb][1], vl[2 * nb + 1][0], vl[2 * nb + 1][1],
                          sb + A_VL + off);
            }
#pragma unroll
            for (int mi = 0; mi < 2; mi++)
#pragma unroll
                for (int ni = 0; ni < 8; ni++) {
                    mma_bf16(accO[mi][ni], ph[mi], vh[ni]);
                    mma_bf16(accO[mi][ni], ph[mi], vl[ni]);
                    mma_bf16(accO[mi][ni], pl[mi], vh[ni]);
                }
        }
        __syncthreads();
    }

#pragma unroll
    for (int mi = 0; mi < 2; mi++) {
        const int r0 = m_off + mi * 16 + erow, r1 = r0 + 8;
        const float i0 = 1.0f / l_s[r0];
        const float i1 = 1.0f / l_s[r1];
        const size_t g0 = ((size_t)(b * SEQ + q0 + r0)) * (NH * HD) + h * HD;
        const size_t g1 = ((size_t)(b * SEQ + q0 + r1)) * (NH * HD) + h * HD;
#pragma unroll
        for (int ni = 0; ni < 8; ni++) {
            const int col = nO + ni * 8 + ecol;
            float o0 = accO[mi][ni][0] * i0, o1 = accO[mi][ni][1] * i0;
            float o2 = accO[mi][ni][2] * i1, o3 = accO[mi][ni][3] * i1;
            __nv_bfloat16 h0 = __float2bfloat16(o0), h1 = __float2bfloat16(o1);
            __nv_bfloat16 h2 = __float2bfloat16(o2), h3 = __float2bfloat16(o3);
            __nv_bfloat162 t;
            t.x = h0; t.y = h1; *(__nv_bfloat162*)(Oh_ + g0 + col) = t;
            t.x = __float2bfloat16(o0 - __bfloat162float(h0));
            t.y = __float2bfloat16(o1 - __bfloat162float(h1));
            *(__nv_bfloat162*)(Ol_ + g0 + col) = t;
            t.x = h2; t.y = h3; *(__nv_bfloat162*)(Oh_ + g1 + col) = t;
            t.x = __float2bfloat16(o2 - __bfloat162float(h2));
            t.y = __float2bfloat16(o3 - __bfloat162float(h3));
            *(__nv_bfloat162*)(Ol_ + g1 + col) = t;
        }
    }
}

// ============================================================
// Launch
// ============================================================
extern "C" void kernel_launch(void* const* d_in, const int* in_sizes, int n_in,
                              void* d_out, int out_size)
{
    (void)in_sizes; (void)n_in; (void)out_size;
    const float* x  = (const float*)d_in[0];
    const float* Wq = (const float*)d_in[2];
    const float* Wk = (const float*)d_in[3];
    const float* Wv = (const float*)d_in[4];
    const float* Wo = (const float*)d_in[5];
    float* out = (float*)d_out;

    float *qb, *kb, *vb;
    cudaGetSymbolAddress((void**)&qb, g_q);
    cudaGetSymbolAddress((void**)&kb, g_k);
    cudaGetSymbolAddress((void**)&vb, g_v);
    __nv_bfloat16 *xh, *xl, *wqh, *wql, *wkh, *wkl, *wvh, *wvl, *woh, *wol;
    __nv_bfloat16 *qsh, *qsl, *ksh, *ksl, *vsh, *vsl, *oh, *ol;
    cudaGetSymbolAddress((void**)&xh, g_xh);   cudaGetSymbolAddress((void**)&xl, g_xl);
    cudaGetSymbolAddress((void**)&wqh, g_wqh); cudaGetSymbolAddress((void**)&wql, g_wql);
    cudaGetSymbolAddress((void**)&wkh, g_wkh); cudaGetSymbolAddress((void**)&wkl, g_wkl);
    cudaGetSymbolAddress((void**)&wvh, g_wvh); cudaGetSymbolAddress((void**)&wvl, g_wvl);
    cudaGetSymbolAddress((void**)&woh, g_woh); cudaGetSymbolAddress((void**)&wol, g_wol);
    cudaGetSymbolAddress((void**)&qsh, g_qsh); cudaGetSymbolAddress((void**)&qsl, g_qsl);
    cudaGetSymbolAddress((void**)&ksh, g_ksh); cudaGetSymbolAddress((void**)&ksl, g_ksl);
    cudaGetSymbolAddress((void**)&vsh, g_vsh); cudaGetSymbolAddress((void**)&vsl, g_vsl);
    cudaGetSymbolAddress((void**)&oh, g_oh);   cudaGetSymbolAddress((void**)&ol, g_ol);

    const int M = BB * SEQ;        // 4096
    const int NX = M * HIDN;

    cudaFuncSetAttribute(gemm_big, cudaFuncAttributeMaxDynamicSharedMemorySize, BG_SMEM);
    cudaFuncSetAttribute(gemm_hmma_split, cudaFuncAttributeMaxDynamicSharedMemorySize, GEMM_SMEM);
    cudaFuncSetAttribute(attn_hmma, cudaFuncAttributeMaxDynamicSharedMemorySize, ATTN_SMEM_B);

    // #1..#3
    split_fp32<<<NX / 256, 256>>>(x, xh, xl, NX);
    transpose_split<<<dim3((NH * HD) / 32, HIDN / 32), dim3(32, 8)>>>(Wq, wqh, wql, HIDN, NH * HD);
    transpose_split<<<dim3((NKV * HD) / 32, HIDN / 32), dim3(32, 8)>>>(Wk, wkh, wkl, HIDN, NKV * HD);
    // #4: big Q projection (ncu-profiled slot)
    gemm_big<<<dim3((NH * HD) / 128, M / 256), 256, BG_SMEM>>>(xh, xl, wqh, wql, qb, NH * HD, HIDN);
    // #5..#8
    transpose_split<<<dim3((NKV * HD) / 32, HIDN / 32), dim3(32, 8)>>>(Wv, wvh, wvl, HIDN, NKV * HD);
    gemm_hmma_split<<<dim3((NKV * HD) / 128, M / 128), 256, GEMM_SMEM>>>(xh, xl, wkh, wkl, kb, NKV * HD, HIDN);
    gemm_hmma_split<<<dim3((NKV * HD) / 128, M / 128), 256, GEMM_SMEM>>>(xh, xl, wvh, wvl, vb, NKV * HD, HIDN);
    transpose_split<<<dim3(HIDN / 32, (NH * HD) / 32), dim3(32, 8)>>>(Wo, woh, wol, NH * HD, HIDN);
    // #9..#11
    rope_split<<<BB * SEQ * NH,  64>>>(qb, qsh, qsl, NH);
    rope_split<<<BB * SEQ * NKV, 64>>>(kb, ksh, ksl, NKV);
    split_v_kernel<<<BB * SEQ * NKV, 128>>>(vb, vsh, vsl);
    // #12
    attn_hmma<<<dim3(SEQ / 128, NH, BB), 256, ATTN_SMEM_B>>>(qsh, qsl, ksh, ksl, vsh, vsl, oh, ol);
    // #13: big O projection
    gemm_big<<<dim3(HIDN / 128, M / 256), 256, BG_SMEM>>>(oh, ol, woh, wol, out, HIDN, NH * HD);
}

// round 8
// speedup vs baseline: 1.4770x; 1.4770x over previous
#include <cuda_runtime.h>
#include <cuda_bf16.h>
#include <math.h>
#include <cstdint>

#define BB   2
#define SEQ  2048
#define HIDN 2048
#define NH   16
#define NKV  4
#define HD   128

// ============================================================
// helpers
// ============================================================
__device__ __forceinline__ uint32_t smem_u32(const void* p) {
    uint32_t a;
    asm("{ .reg .u64 t; cvta.to.shared.u64 t, %1; cvt.u32.u64 %0, t; }" : "=r"(a) : "l"(p));
    return a;
}
__device__ __forceinline__ void ldsm_x4(uint32_t& r0, uint32_t& r1, uint32_t& r2, uint32_t& r3,
                                        uint32_t addr) {
    asm volatile("ldmatrix.sync.aligned.m8n8.x4.shared.b16 {%0,%1,%2,%3}, [%4];"
                 : "=r"(r0), "=r"(r1), "=r"(r2), "=r"(r3) : "r"(addr));
}
__device__ __forceinline__ void ldsm_x4_t(uint32_t& r0, uint32_t& r1, uint32_t& r2, uint32_t& r3,
                                          uint32_t addr) {
    asm volatile("ldmatrix.sync.aligned.m8n8.x4.trans.shared.b16 {%0,%1,%2,%3}, [%4];"
                 : "=r"(r0), "=r"(r1), "=r"(r2), "=r"(r3) : "r"(addr));
}
__device__ __forceinline__ void mma_bf16(float* c, const uint32_t* a, const uint32_t* b) {
    asm volatile("mma.sync.aligned.m16n8k16.row.col.f32.bf16.bf16.f32 "
                 "{%0,%1,%2,%3}, {%4,%5,%6,%7}, {%8,%9}, {%0,%1,%2,%3};"
                 : "+f"(c[0]), "+f"(c[1]), "+f"(c[2]), "+f"(c[3])
                 : "r"(a[0]), "r"(a[1]), "r"(a[2]), "r"(a[3]), "r"(b[0]), "r"(b[1]));
}
__device__ __forceinline__ void cp_async16(uint32_t saddr, const void* gptr) {
    asm volatile("cp.async.cg.shared.global [%0], [%1], 16;"
                 :: "r"(saddr), "l"(__cvta_generic_to_global(gptr)));
}
// fast 2^t on the FMA pipe, t <= 0
__device__ __forceinline__ float fexp2(float t) {
    t = fmaxf(t, -126.0f);
    float fi = floorf(t);
    float f = t - fi;
    float p =             1.5403530e-4f;
    p = fmaf(p, f, 1.3333558e-3f);
    p = fmaf(p, f, 9.6181291e-3f);
    p = fmaf(p, f, 5.5504109e-2f);
    p = fmaf(p, f, 2.4022651e-1f);
    p = fmaf(p, f, 6.9314718e-1f);
    p = fmaf(p, f, 1.0f);
    return p * __int_as_float(((int)fi + 127) << 23);
}

// -------- scratch (device globals) --------
__device__ __nv_bfloat16 g_xh[(size_t)BB * SEQ * HIDN], g_xl[(size_t)BB * SEQ * HIDN];
__device__ __nv_bfloat16 g_wqh[(size_t)HIDN * NH * HD], g_wql[(size_t)HIDN * NH * HD];
__device__ __nv_bfloat16 g_wkh[(size_t)HIDN * NKV * HD], g_wkl[(size_t)HIDN * NKV * HD];
__device__ __nv_bfloat16 g_wvh[(size_t)HIDN * NKV * HD], g_wvl[(size_t)HIDN * NKV * HD];
__device__ __nv_bfloat16 g_woh[(size_t)NH * HD * HIDN], g_wol[(size_t)NH * HD * HIDN];

// head-major split operands for attention: [b, head, s, d]
__device__ __nv_bfloat16 g_qsh[(size_t)BB * NH * SEQ * HD],  g_qsl[(size_t)BB * NH * SEQ * HD];
__device__ __nv_bfloat16 g_ksh[(size_t)BB * NKV * SEQ * HD], g_ksl[(size_t)BB * NKV * SEQ * HD];
__device__ __nv_bfloat16 g_vsh[(size_t)BB * NKV * SEQ * HD], g_vsl[(size_t)BB * NKV * SEQ * HD];
// attention output, split, [B*S, H*D]
__device__ __nv_bfloat16 g_oh[(size_t)BB * SEQ * NH * HD],  g_ol[(size_t)BB * SEQ * NH * HD];

// ============================================================
// fp32 -> (hi, lo) bf16 split
// ============================================================
__global__ void split_fp32(const float* __restrict__ x,
                           __nv_bfloat16* __restrict__ h, __nv_bfloat16* __restrict__ l, int n)
{
    int i = blockIdx.x * blockDim.x + threadIdx.x;
    if (i < n) {
        float v = x[i];
        __nv_bfloat16 hi = __float2bfloat16(v);
        h[i] = hi;
        l[i] = __float2bfloat16(v - __bfloat162float(hi));
    }
}

// ============================================================
// W[K,N] fp32 -> Wt_hi/Wt_lo [N,K] bf16 (transpose + split)
// ============================================================
__global__ void transpose_split(const float* __restrict__ W,
                                __nv_bfloat16* __restrict__ Th, __nv_bfloat16* __restrict__ Tl,
                                int K, int N)
{
    __shared__ float t[32][33];
    const int n0 = blockIdx.x * 32, k0 = blockIdx.y * 32;
    const int tx = threadIdx.x, ty = threadIdx.y;
    for (int i = ty; i < 32; i += 8)
        t[i][tx] = W[(size_t)(k0 + i) * N + n0 + tx];
    __syncthreads();
    for (int i = ty; i < 32; i += 8) {
        float v = t[tx][i];
        __nv_bfloat16 hi = __float2bfloat16(v);
        float r = v - __bfloat162float(hi);
        Th[(size_t)(n0 + i) * K + k0 + tx] = hi;
        Tl[(size_t)(n0 + i) * K + k0 + tx] = __float2bfloat16(r);
    }
}

#define LDA 40

// ============================================================
// gemm3: 128x128 CTA tile, 64x32 warp tile, BK=32,
// 3-stage cp.async pipeline with ONE barrier per chunk.
// C = (Ah+Al) @ (Bh+Bl)^T via 3-term split, fp32 accum.
// Epilogue: epi==0 -> fp32 row-major C.
//           epi==1 -> split bf16 head-major [b, n>>7, s, n&127].
// ============================================================
#define G3_TILE (128 * LDA * 2)       // 10240 B
#define G3_STAGE (4 * G3_TILE)        // 40960 B
#define G3_SMEM (3 * G3_STAGE)        // 122880 B

__global__ void __launch_bounds__(256, 1) gemm3(
    const __nv_bfloat16* __restrict__ Ah_, const __nv_bfloat16* __restrict__ Al_,
    const __nv_bfloat16* __restrict__ Bh_, const __nv_bfloat16* __restrict__ Bl_,
    float* __restrict__ Cf, __nv_bfloat16* __restrict__ Ch, __nv_bfloat16* __restrict__ Cl,
    int Nd, int Kd, int heads, int epi)
{
    extern __shared__ char sm[];
    const uint32_t sb = smem_u32(sm);
    const int tid = threadIdx.x, lane = tid & 31, wid = tid >> 5;
    const int m0 = blockIdx.y * 128, n0 = blockIdx.x * 128;
    const int m_off = (wid >> 2) * 64;
    const int n_off = (wid & 3) * 32;

    const int r0 = tid >> 2;
    const int c8 = (tid & 3) * 8;

    const __nv_bfloat16* gp[4] = {
        Ah_ + (size_t)m0 * Kd, Al_ + (size_t)m0 * Kd,
        Bh_ + (size_t)n0 * Kd, Bl_ + (size_t)n0 * Kd };

    const int nchunk = Kd >> 5;

    auto load_chunk = [&](int c) {
        const int k0 = c << 5;
        const uint32_t stg = sb + (uint32_t)(c % 3) * G3_STAGE;
#pragma unroll
        for (int t = 0; t < 4; t++) {
#pragma unroll
            for (int p = 0; p < 2; p++) {
                const int r = r0 + p * 64;
                cp_async16(stg + (uint32_t)t * G3_TILE + (uint32_t)(r * LDA + c8) * 2,
                           gp[t] + (size_t)r * Kd + k0 + c8);
            }
        }
        asm volatile("cp.async.commit_group;" ::: "memory");
    };

    const int a_row = ((lane >> 3) & 1) * 8 + (lane & 7);
    const int a_kh  = (lane >> 4) * 8;
    const int b_row = ((lane >> 4) & 1) * 8 + (lane & 7);
    const int b_kh  = ((lane >> 3) & 1) * 8;

    float acc[4][4][4];
#pragma unroll
    for (int i = 0; i < 4; i++)
#pragma unroll
        for (int j = 0; j < 4; j++)
#pragma unroll
            for (int q = 0; q < 4; q++) acc[i][j][q] = 0.f;

    load_chunk(0);
    load_chunk(1);

    for (int c = 0; c < nchunk; c++) {
        if (c < nchunk - 1) {
            asm volatile("cp.async.wait_group 1;" ::: "memory");
        } else {
            asm volatile("cp.async.wait_group 0;" ::: "memory");
        }
        __syncthreads();
        if (c + 2 < nchunk) load_chunk(c + 2);   // stage freed by the barrier

        const uint32_t stg = sb + (uint32_t)(c % 3) * G3_STAGE;
        const uint32_t sAh = stg;
        const uint32_t sAl = stg + G3_TILE;
        const uint32_t sBh = stg + 2 * G3_TILE;
        const uint32_t sBl = stg + 3 * G3_TILE;

#pragma unroll
        for (int ks = 0; ks < 2; ks++) {
            uint32_t ah[4][4], al[4][4], bh[4][2], bl[4][2];
#pragma unroll
            for (int mi = 0; mi < 4; mi++) {
                const uint32_t off =
                    (uint32_t)((m_off + mi * 16 + a_row) * LDA + ks * 16 + a_kh) * 2;
                ldsm_x4(ah[mi][0], ah[mi][1], ah[mi][2], ah[mi][3], sAh + off);
                ldsm_x4(al[mi][0], al[mi][1], al[mi][2], al[mi][3], sAl + off);
            }
#pragma unroll
            for (int nb = 0; nb < 2; nb++) {
                const uint32_t off =
                    (uint32_t)((n_off + nb * 16 + b_row) * LDA + ks * 16 + b_kh) * 2;
                ldsm_x4(bh[2 * nb][0], bh[2 * nb][1], bh[2 * nb + 1][0], bh[2 * nb + 1][1],
                        sBh + off);
                ldsm_x4(bl[2 * nb][0], bl[2 * nb][1], bl[2 * nb + 1][0], bl[2 * nb + 1][1],
                        sBl + off);
            }
#pragma unroll
            for (int mi = 0; mi < 4; mi++)
#pragma unroll
                for (int ni = 0; ni < 4; ni++) {
                    mma_bf16(acc[mi][ni], ah[mi], bh[ni]);
                    mma_bf16(acc[mi][ni], ah[mi], bl[ni]);
                    mma_bf16(acc[mi][ni], al[mi], bh[ni]);
                }
        }
    }

    const int erow = lane >> 2, ecol = (lane & 3) * 2;
    if (epi == 0) {
#pragma unroll
        for (int mi = 0; mi < 4; mi++)
#pragma unroll
            for (int ni = 0; ni < 4; ni++) {
                const int row = m0 + m_off + mi * 16 + erow;
                const int col = n0 + n_off + ni * 8 + ecol;
                float2 v0 = make_float2(acc[mi][ni][0], acc[mi][ni][1]);
                float2 v1 = make_float2(acc[mi][ni][2], acc[mi][ni][3]);
                *(float2*)(Cf + (size_t)row * Nd + col)       = v0;
                *(float2*)(Cf + (size_t)(row + 8) * Nd + col) = v1;
            }
    } else {
        // split bf16, head-major [b, h, s, d]; row = b*SEQ + s, col = h*HD + d
#pragma unroll
        for (int mi = 0; mi < 4; mi++)
#pragma unroll
            for (int ni = 0; ni < 4; ni++) {
                const int col = n0 + n_off + ni * 8 + ecol;
                const int hh = col >> 7, d = col & 127;
#pragma unroll
                for (int rr = 0; rr < 2; rr++) {
                    const int row = m0 + m_off + mi * 16 + erow + rr * 8;
                    const int bb = row >> 11, s = row & (SEQ - 1);
                    const size_t g = ((size_t)(bb * heads + hh) * SEQ + s) * HD + d;
                    float v0 = acc[mi][ni][rr * 2 + 0];
                    float v1 = acc[mi][ni][rr * 2 + 1];
                    __nv_bfloat16 h0 = __float2bfloat16(v0);
                    __nv_bfloat16 h1 = __float2bfloat16(v1);
                    __nv_bfloat162 hp; hp.x = h0; hp.y = h1;
                    *(__nv_bfloat162*)(Ch + g) = hp;
                    __nv_bfloat162 lp;
                    lp.x = __float2bfloat16(v0 - __bfloat162float(h0));
                    lp.y = __float2bfloat16(v1 - __bfloat162float(h1));
                    *(__nv_bfloat162*)(Cl + g) = lp;
                }
            }
    }
}

// ============================================================
// RoPE in-place on split bf16 head-major rows [*, 128]
// ============================================================
__global__ void rope_inplace(__nv_bfloat16* __restrict__ h, __nv_bfloat16* __restrict__ l)
{
    const int idx = blockIdx.x;            // (b*heads + hh)*SEQ + s
    const int s = idx & (SEQ - 1);
    const size_t base = (size_t)idx * HD;
    const int i = threadIdx.x;             // 0..63

    float x0 = __bfloat162float(h[base + 2 * i])     + __bfloat162float(l[base + 2 * i]);
    float x1 = __bfloat162float(h[base + 2 * i + 1]) + __bfloat162float(l[base + 2 * i + 1]);
    float inv = exp2f(-(float)i * (13.287712379549449f / 64.f));
    float ang = (float)s * inv;
    float sn, cs;
    sincosf(ang, &sn, &cs);
    float o0 = x0 * cs - x1 * sn;
    float o1 = x0 * sn + x1 * cs;
    __syncthreads();   // all reads before any writes
    __nv_bfloat16 h0 = __float2bfloat16(o0);
    __nv_bfloat16 h1 = __float2bfloat16(o1);
    h[base + i]      = h0;
    h[base + i + 64] = h1;
    l[base + i]      = __float2bfloat16(o0 - __bfloat162float(h0));
    l[base + i + 64] = __float2bfloat16(o1 - __bfloat162float(h1));
}

// ============================================================
// HMMA flash attention (unchanged from R6)
// ============================================================
#define ALDQ 136
#define ALDS 73
#define ALDP 72
#define A_QH 0
#define A_QL (A_QH + 128 * ALDQ * 2)
#define A_KH (A_QL + 128 * ALDQ * 2)
#define A_KL (A_KH + 64 * ALDQ * 2)
#define A_VH (A_KL + 64 * ALDQ * 2)
#define A_VL (A_VH + 64 * ALDQ * 2)
#define A_SP (A_VL + 64 * ALDQ * 2)
#define A_PH (A_SP + 128 * ALDS * 4)
#define A_PL (A_PH + 128 * ALDP * 2)
#define A_MS (A_PL + 128 * ALDP * 2)
#define A_LS (A_MS + 512)
#define A_FS (A_LS + 512)
#define A_RED (A_FS + 512)
#define ATTN_SMEM_B (A_RED + 1024)

#define SCL2E 0.12751744f

__global__ void __launch_bounds__(256, 1) attn_hmma(
    const __nv_bfloat16* __restrict__ Qh_, const __nv_bfloat16* __restrict__ Ql_,
    const __nv_bfloat16* __restrict__ Kh_, const __nv_bfloat16* __restrict__ Kl_,
    const __nv_bfloat16* __restrict__ Vh_, const __nv_bfloat16* __restrict__ Vl_,
    __nv_bfloat16* __restrict__ Oh_, __nv_bfloat16* __restrict__ Ol_)
{
    extern __shared__ char sm[];
    const uint32_t sb = smem_u32(sm);
    float* Sp  = (float*)(sm + A_SP);
    float* m_s = (float*)(sm + A_MS);
    float* l_s = (float*)(sm + A_LS);
    float* f_s = (float*)(sm + A_FS);
    float* red = (float*)(sm + A_RED);
    __nv_bfloat16* PhP = (__nv_bfloat16*)(sm + A_PH);
    __nv_bfloat16* PlP = (__nv_bfloat16*)(sm + A_PL);

    const int qb = blockIdx.x, h = blockIdx.y, b = blockIdx.z;
    const int kvh = h >> 2;
    const int tid = threadIdx.x, lane = tid & 31, wid = tid >> 5;
    const int q0 = qb * 128;

    const size_t qg = ((size_t)(b * NH + h) * SEQ + q0) * HD;
    const size_t kg = (size_t)(b * NKV + kvh) * SEQ * HD;

    for (int i = tid; i < 128 * 16; i += 256) {
        int r = i >> 4, c = (i & 15) * 8;
        uint32_t so = (uint32_t)(r * ALDQ + c) * 2;
        cp_async16(sb + A_QH + so, Qh_ + qg + (size_t)r * HD + c);
        cp_async16(sb + A_QL + so, Ql_ + qg + (size_t)r * HD + c);
    }
    asm volatile("cp.async.commit_group;" ::: "memory");
    if (tid < 128) { m_s[tid] = -1e30f; l_s[tid] = 0.f; }

    float accO[2][8][4];
#pragma unroll
    for (int i = 0; i < 2; i++)
#pragma unroll
        for (int j = 0; j < 8; j++)
#pragma unroll
            for (int q = 0; q < 4; q++) accO[i][j][q] = 0.f;

    const int m_off = (wid >> 1) * 32;
    const int nS = (wid & 1) * 32;
    const int nO = (wid & 1) * 64;
    const int a_row = ((lane >> 3) & 1) * 8 + (lane & 7);
    const int a_kh  = (lane >> 4) * 8;
    const int b_row = ((lane >> 4) & 1) * 8 + (lane & 7);
    const int b_kh  = ((lane >> 3) & 1) * 8;
    const int erow = lane >> 2, ecol = (lane & 3) * 2;

    asm volatile("cp.async.wait_group 0;" ::: "memory");
    __syncthreads();

    const int ntiles = 2 * qb + 2;
    for (int jb = 0; jb < ntiles; jb++) {
        const int k0 = jb * 64;
        for (int i = tid; i < 64 * 16; i += 256) {
            int r = i >> 4, c = (i & 15) * 8;
            uint32_t so = (uint32_t)(r * ALDQ + c) * 2;
            const size_t g = kg + (size_t)(k0 + r) * HD + c;
            cp_async16(sb + A_KH + so, Kh_ + g);
            cp_async16(sb + A_KL + so, Kl_ + g);
            cp_async16(sb + A_VH + so, Vh_ + g);
            cp_async16(sb + A_VL + so, Vl_ + g);
        }
        asm volatile("cp.async.commit_group;" ::: "memory");
        asm volatile("cp.async.wait_group 0;" ::: "memory");
        __syncthreads();

        float accS[2][4][4];
#pragma unroll
        for (int i = 0; i < 2; i++)
#pragma unroll
            for (int j = 0; j < 4; j++)
#pragma unroll
                for (int q = 0; q < 4; q++) accS[i][j][q] = 0.f;

#pragma unroll
        for (int ks = 0; ks < 8; ks++) {
            uint32_t ah[2][4], al[2][4], bh[4][2], bl[4][2];
#pragma unroll
            for (int mi = 0; mi < 2; mi++) {
                const uint32_t off =
                    (uint32_t)((m_off + mi * 16 + a_row) * ALDQ + ks * 16 + a_kh) * 2;
                ldsm_x4(ah[mi][0], ah[mi][1], ah[mi][2], ah[mi][3], sb + A_QH + off);
                ldsm_x4(al[mi][0], al[mi][1], al[mi][2], al[mi][3], sb + A_QL + off);
            }
#pragma unroll
            for (int nb = 0; nb < 2; nb++) {
                const uint32_t off =
                    (uint32_t)((nS + nb * 16 + b_row) * ALDQ + ks * 16 + b_kh) * 2;
                ldsm_x4(bh[2 * nb][0], bh[2 * nb][1], bh[2 * nb + 1][0], bh[2 * nb + 1][1],
                        sb + A_KH + off);
                ldsm_x4(bl[2 * nb][0], bl[2 * nb][1], bl[2 * nb + 1][0], bl[2 * nb + 1][1],
                        sb + A_KL + off);
            }
#pragma unroll
            for (int mi = 0; mi < 2; mi++)
#pragma unroll
                for (int ni = 0; ni < 4; ni++) {
                    mma_bf16(accS[mi][ni], ah[mi], bh[ni]);
                    mma_bf16(accS[mi][ni], ah[mi], bl[ni]);
                    mma_bf16(accS[mi][ni], al[mi], bh[ni]);
                }
        }

#pragma unroll
        for (int mi = 0; mi < 2; mi++)
#pragma unroll
            for (int ni = 0; ni < 4; ni++) {
                const int row = m_off + mi * 16 + erow;
                const int col = nS + ni * 8 + ecol;
                Sp[row * ALDS + col]           = accS[mi][ni][0] * SCL2E;
                Sp[row * ALDS + col + 1]       = accS[mi][ni][1] * SCL2E;
                Sp[(row + 8) * ALDS + col]     = accS[mi][ni][2] * SCL2E;
                Sp[(row + 8) * ALDS + col + 1] = accS[mi][ni][3] * SCL2E;
            }
        __syncthreads();

        {
            const int row = tid & 127, part = tid >> 7;
            const int cb = part * 32;
            float mx = -1e30f;
#pragma unroll
            for (int c = 0; c < 32; c++) {
                const int cc = cb + c;
                float s = Sp[row * ALDS + cc];
                if (k0 + cc > q0 + row) s = -1e30f;
                mx = fmaxf(mx, s);
            }
            red[part * 128 + row] = mx;
            __syncthreads();
            if (part == 0) {
                float mo = m_s[row];
                float mn = fmaxf(mo, fmaxf(red[row], red[128 + row]));
                m_s[row] = mn;
                f_s[row] = fexp2(mo - mn);
            }
            __syncthreads();
            const float mrow = m_s[row];
            float sum = 0.f;
#pragma unroll
            for (int c = 0; c < 16; c++) {
                const int cc = cb + c * 2;
                float s0 = Sp[row * ALDS + cc];
                float s1 = Sp[row * ALDS + cc + 1];
                float p0 = (k0 + cc     > q0 + row) ? 0.f : fexp2(s0 - mrow);
                float p1 = (k0 + cc + 1 > q0 + row) ? 0.f : fexp2(s1 - mrow);
                sum += p0 + p1;
                __nv_bfloat16 h0 = __float2bfloat16(p0);
                __nv_bfloat16 h1 = __float2bfloat16(p1);
                __nv_bfloat162 hp; hp.x = h0; hp.y = h1;
                *(__nv_bfloat162*)(PhP + row * ALDP + cc) = hp;
                __nv_bfloat162 lp;
                lp.x = __float2bfloat16(p0 - __bfloat162float(h0));
                lp.y = __float2bfloat16(p1 - __bfloat162float(h1));
                *(__nv_bfloat162*)(PlP + row * ALDP + cc) = lp;
            }
            red[part * 128 + row] = sum;
            __syncthreads();
            if (part == 0)
                l_s[row] = l_s[row] * f_s[row] + red[row] + red[128 + row];
        }
        __syncthreads();

#pragma unroll
        for (int mi = 0; mi < 2; mi++) {
            const float f0 = f_s[m_off + mi * 16 + erow];
            const float f1 = f_s[m_off + mi * 16 + erow + 8];
#pragma unroll
            for (int ni = 0; ni < 8; ni++) {
                accO[mi][ni][0] *= f0; accO[mi][ni][1] *= f0;
                accO[mi][ni][2] *= f1; accO[mi][ni][3] *= f1;
            }
        }
#pragma unroll
        for (int kk = 0; kk < 4; kk++) {
            uint32_t ph[2][4], pl[2][4], vh[8][2], vl[8][2];
#pragma unroll
            for (int mi = 0; mi < 2; mi++) {
                const uint32_t off =
                    (uint32_t)((m_off + mi * 16 + a_row) * ALDP + kk * 16 + a_kh) * 2;
                ldsm_x4(ph[mi][0], ph[mi][1], ph[mi][2], ph[mi][3], sb + A_PH + off);
                ldsm_x4(pl[mi][0], pl[mi][1], pl[mi][2], pl[mi][3], sb + A_PL + off);
            }
#pragma unroll
            for (int nb = 0; nb < 4; nb++) {
                const int vr = kk * 16 + ((lane >> 3) & 1) * 8 + (lane & 7);
                const int vc = nO + nb * 16 + ((lane >> 4) & 1) * 8;
                const uint32_t off = (uint32_t)(vr * ALDQ + vc) * 2;
                ldsm_x4_t(vh[2 * nb][0], vh[2 * nb][1], vh[2 * nb + 1][0], vh[2 * nb + 1][1],
                          sb + A_VH + off);
                ldsm_x4_t(vl[2 * nb][0], vl[2 * nb][1], vl[2 * nb + 1][0], vl[2 * nb + 1][1],
                          sb + A_VL + off);
            }
#pragma unroll
            for (int mi = 0; mi < 2; mi++)
#pragma unroll
                for (int ni = 0; ni < 8; ni++) {
                    mma_bf16(accO[mi][ni], ph[mi], vh[ni]);
                    mma_bf16(accO[mi][ni], ph[mi], vl[ni]);
                    mma_bf16(accO[mi][ni], pl[mi], vh[ni]);
                }
        }
        __syncthreads();
    }

#pragma unroll
    for (int mi = 0; mi < 2; mi++) {
        const int r0 = m_off + mi * 16 + erow, r1 = r0 + 8;
        const float i0 = 1.0f / l_s[r0];
        const float i1 = 1.0f / l_s[r1];
        const size_t g0 = ((size_t)(b * SEQ + q0 + r0)) * (NH * HD) + h * HD;
        const size_t g1 = ((size_t)(b * SEQ + q0 + r1)) * (NH * HD) + h * HD;
#pragma unroll
        for (int ni = 0; ni < 8; ni++) {
            const int col = nO + ni * 8 + ecol;
            float o0 = accO[mi][ni][0] * i0, o1 = accO[mi][ni][1] * i0;
            float o2 = accO[mi][ni][2] * i1, o3 = accO[mi][ni][3] * i1;
            __nv_bfloat16 h0 = __float2bfloat16(o0), h1 = __float2bfloat16(o1);
            __nv_bfloat16 h2 = __float2bfloat16(o2), h3 = __float2bfloat16(o3);
            __nv_bfloat162 t;
            t.x = h0; t.y = h1; *(__nv_bfloat162*)(Oh_ + g0 + col) = t;
            t.x = __float2bfloat16(o0 - __bfloat162float(h0));
            t.y = __float2bfloat16(o1 - __bfloat162float(h1));
            *(__nv_bfloat162*)(Ol_ + g0 + col) = t;
            t.x = h2; t.y = h3; *(__nv_bfloat162*)(Oh_ + g1 + col) = t;
            t.x = __float2bfloat16(o2 - __bfloat162float(h2));
            t.y = __float2bfloat16(o3 - __bfloat162float(h3));
            *(__nv_bfloat162*)(Ol_ + g1 + col) = t;
        }
    }
}

// ============================================================
// Launch
// ============================================================
extern "C" void kernel_launch(void* const* d_in, const int* in_sizes, int n_in,
                              void* d_out, int out_size)
{
    (void)in_sizes; (void)n_in; (void)out_size;
    const float* x  = (const float*)d_in[0];
    const float* Wq = (const float*)d_in[2];
    const float* Wk = (const float*)d_in[3];
    const float* Wv = (const float*)d_in[4];
    const float* Wo = (const float*)d_in[5];
    float* out = (float*)d_out;

    __nv_bfloat16 *xh, *xl, *wqh, *wql, *wkh, *wkl, *wvh, *wvl, *woh, *wol;
    __nv_bfloat16 *qsh, *qsl, *ksh, *ksl, *vsh, *vsl, *oh, *ol;
    cudaGetSymbolAddress((void**)&xh, g_xh);   cudaGetSymbolAddress((void**)&xl, g_xl);
    cudaGetSymbolAddress((void**)&wqh, g_wqh); cudaGetSymbolAddress((void**)&wql, g_wql);
    cudaGetSymbolAddress((void**)&wkh, g_wkh); cudaGetSymbolAddress((void**)&wkl, g_wkl);
    cudaGetSymbolAddress((void**)&wvh, g_wvh); cudaGetSymbolAddress((void**)&wvl, g_wvl);
    cudaGetSymbolAddress((void**)&woh, g_woh); cudaGetSymbolAddress((void**)&wol, g_wol);
    cudaGetSymbolAddress((void**)&qsh, g_qsh); cudaGetSymbolAddress((void**)&qsl, g_qsl);
    cudaGetSymbolAddress((void**)&ksh, g_ksh); cudaGetSymbolAddress((void**)&ksl, g_ksl);
    cudaGetSymbolAddress((void**)&vsh, g_vsh); cudaGetSymbolAddress((void**)&vsl, g_vsl);
    cudaGetSymbolAddress((void**)&oh, g_oh);   cudaGetSymbolAddress((void**)&ol, g_ol);

    const int M = BB * SEQ;        // 4096
    const int NX = M * HIDN;

    cudaFuncSetAttribute(gemm3, cudaFuncAttributeMaxDynamicSharedMemorySize, G3_SMEM);
    cudaFuncSetAttribute(attn_hmma, cudaFuncAttributeMaxDynamicSharedMemorySize, ATTN_SMEM_B);

    // #1..#3
    split_fp32<<<NX / 256, 256>>>(x, xh, xl, NX);
    transpose_split<<<dim3((NH * HD) / 32, HIDN / 32), dim3(32, 8)>>>(Wq, wqh, wql, HIDN, NH * HD);
    transpose_split<<<dim3((NKV * HD) / 32, HIDN / 32), dim3(32, 8)>>>(Wk, wkh, wkl, HIDN, NKV * HD);
    // #4: Q projection (ncu-profiled slot) -> split bf16 head-major
    gemm3<<<dim3((NH * HD) / 128, M / 128), 256, G3_SMEM>>>(
        xh, xl, wqh, wql, nullptr, qsh, qsl, NH * HD, HIDN, NH, 1);
    // #5..#8
    transpose_split<<<dim3((NKV * HD) / 32, HIDN / 32), dim3(32, 8)>>>(Wv, wvh, wvl, HIDN, NKV * HD);
    gemm3<<<dim3((NKV * HD) / 128, M / 128), 256, G3_SMEM>>>(
        xh, xl, wkh, wkl, nullptr, ksh, ksl, NKV * HD, HIDN, NKV, 1);
    gemm3<<<dim3((NKV * HD) / 128, M / 128), 256, G3_SMEM>>>(
        xh, xl, wvh, wvl, nullptr, vsh, vsl, NKV * HD, HIDN, NKV, 1);
    transpose_split<<<dim3(HIDN / 32, (NH * HD) / 32), dim3(32, 8)>>>(Wo, woh, wol, NH * HD, HIDN);
    // #9..#10: RoPE in-place on split bf16
    rope_inplace<<<BB * NH * SEQ,  64>>>(qsh, qsl);
    rope_inplace<<<BB * NKV * SEQ, 64>>>(ksh, ksl);
    // #11
    attn_hmma<<<dim3(SEQ / 128, NH, BB), 256, ATTN_SMEM_B>>>(qsh, qsl, ksh, ksl, vsh, vsl, oh, ol);
    // #12: output projection -> fp32 d_out
    gemm3<<<dim3(HIDN / 128, M / 128), 256, G3_SMEM>>>(
        oh, ol, woh, wol, out, nullptr, nullptr, HIDN, NH * HD, 0, 0);
}